// round 11
// baseline (speedup 1.0000x reference)
#include <cuda_runtime.h>
#include <cuda_bf16.h>

#define FULLMASK 0xffffffffu
typedef unsigned long long u64;

// Packed f32x2 helpers (sm_103a). add/mul/fma.rn.f32x2 round each 32-bit half
// exactly like the scalar .rn ops -> bit-identical to the reference dataflow.
__device__ __forceinline__ u64 pk(float lo, float hi) {
    u64 r; asm("mov.b64 %0,{%1,%2};" : "=l"(r) : "f"(lo), "f"(hi)); return r;
}
__device__ __forceinline__ void upk(u64 v, float& lo, float& hi) {
    asm("mov.b64 {%0,%1},%2;" : "=f"(lo), "=f"(hi) : "l"(v));
}
__device__ __forceinline__ u64 f2add(u64 a, u64 b) {
    u64 r; asm("add.rn.f32x2 %0,%1,%2;" : "=l"(r) : "l"(a), "l"(b)); return r;
}
__device__ __forceinline__ u64 f2mul(u64 a, u64 b) {
    u64 r; asm("mul.rn.f32x2 %0,%1,%2;" : "=l"(r) : "l"(a), "l"(b)); return r;
}
__device__ __forceinline__ u64 f2fma(u64 a, u64 b, u64 c) {
    u64 r; asm("fma.rn.f32x2 %0,%1,%2,%3;" : "=l"(r) : "l"(a), "l"(b), "l"(c)); return r;
}

// One warp per 32x32 patch, lane = column. Two rows per iteration.
// Sobel front f32x2-packed (halves the shfl count); post-atan2 tail is pure
// scalar (packed tail's pack/unpack MOVs cost more than the packed ops save).
// 8x-scaled gradient domain (exact power-of-2; EPS pre-scaled).
// LESSON (R8): every float feeding the histogram weights follows the
// reference's exact rounding chain (rn mul/add, sqrt.rn, libdevice atan2f).
// Division by 2*pi via scalar Markstein fma (correctly rounded == div.rn).
// floor clamped to 71 (exact re-routing of ob==72) -> 38-row per-lane
// histogram, row = floor-35; rows 0/37 alias bins 35/0, folded at reduce.
// hist[row][lane]: bank == lane, conflict-free, no atomics.
// Epilogue: pairwise rotated LDS.64 reduce (tolerated ordering-noise class).

__global__ void __launch_bounds__(64, 23)
pdgo_kernel(const float* __restrict__ patches, float* __restrict__ out, int B)
{
    __shared__ float hist[2][38 * 32];   // 9728 B/block -> 23 blocks/SM

    const int warp = threadIdx.x >> 5;
    const int lane = threadIdx.x & 31;
    const int pIdx = blockIdx.x * 2 + warp;
    if (pIdx >= B) return;

    float* hw = hist[warp];
    float* hl = hw + lane;

    #pragma unroll
    for (int b = 0; b < 38; ++b) hw[b * 32 + lane] = 0.0f;
    __syncwarp();

    const float* p = patches + (size_t)pIdx * 1024 + lane;

    constexpr float C2PI   = 6.28318530717958647692f;   // f32 2*pi (0x40C90FDB)
    constexpr float CPI    = 3.14159265358979323846f;
    constexpr float RCP2PI = 1.0f / C2PI;               // rn reciprocal, folded

    const u64 TWO2   = pk(2.0f, 2.0f);
    const u64 EPS8   = pk(8e-8f, 8e-8f);     // 8 * f32(1e-8), exact scaling
    const u64 EPS64  = pk(6.4e-7f, 6.4e-7f); // 64 * f32(1e-8), exact scaling
    const u64 NONE2  = pk(-1.0f, -1.0f);

    // scalar per-pixel tail: exact reference rounding chain
    auto tail = [&](float uyv, float xsv, float m2v) {
        float mag = __fsqrt_rn(m2v);                   // 8*mag, exact
        float ori = atan2f(uyv, xsv);                  // scale-invariant
        float t1  = __fadd_rn(ori, C2PI);
        float t2  = __fadd_rn(t1, CPI);
        float t3  = __fmul_rn(36.0f, t2);
        // ob = rn(t3 / 2pi) via Markstein (correctly rounded == div.rn)
        float q0  = __fmul_rn(t3, RCP2PI);
        float rr  = __fmaf_rn(-C2PI, q0, t3);          // exact residual
        float ob  = __fmaf_rn(rr, RCP2PI, q0);
        // clamp floor to 71: ob==72 re-routes exactly (w1f 0 -> 1; mag to bin 0)
        float fb  = fminf(floorf(ob), 71.0f);
        float w1f = __fsub_rn(ob, fb);
        float w0  = __fmul_rn(__fsub_rn(1.0f, w1f), mag);
        float w1  = __fmul_rn(w1f, mag);
        int row = (int)fb * 32 - 35 * 32;              // rows 0..36 (+32 -> 1..37)
        hl[row]      += w0;
        hl[row + 32] += w1;
    };

    // rows (r, r+1): lo half = row r, hi half = row r+1; window rm1..r2
    auto pair_body = [&](float rm1, float r0v, float r1v, float r2v) {
        u64 cv = pk(r0v, r1v);
        u64 pv = pk(rm1, r0v);
        u64 nv = pk(r1v, r2v);
        // t = (2*c + p) + n ; rn(2c+p) == rn((c+c)+p) since 2c is exact
        u64 t2x = f2add(f2fma(TWO2, cv, pv), nv);
        u64 dd2 = f2fma(pv, NONE2, nv);               // rn(n - p), exact fold

        u64 tl = __shfl_up_sync(FULLMASK, t2x, 1);    // lane0 keeps own -> edge pad
        u64 tr = __shfl_down_sync(FULLMASK, t2x, 1);  // lane31 keeps own -> edge pad
        u64 dl = __shfl_up_sync(FULLMASK, dd2, 1);
        u64 dr = __shfl_down_sync(FULLMASK, dd2, 1);

        u64 ux2 = f2fma(tl, NONE2, tr);               // rn(tr - tl) = 8*gx
        u64 uy2 = f2add(f2fma(TWO2, dd2, dl), dr);    // 8*gy

        u64 xs2 = f2add(ux2, EPS8);                   // 8*(gx+eps), exact .rn
        // m2: reference rounding order -- rn(rn(ux^2) + rn(uy^2)) + eps
        u64 m22 = f2add(f2add(f2mul(ux2, ux2), f2mul(uy2, uy2)), EPS64);

        float m2l, m2h, uyl, uyh, xsl, xsh;
        upk(m22, m2l, m2h);
        upk(uy2, uyl, uyh);
        upk(xs2, xsl, xsh);
        tail(uyl, xsl, m2l);
        tail(uyh, xsh, m2h);
    };

    float r0v = __ldcs(p);        // row 0
    float rm1 = r0v;              // edge pad: row -1 == row 0

    #pragma unroll 3
    for (int k = 0; k < 15; ++k) {
        float r1v = __ldcs(p + (2 * k + 1) * 32);
        float r2v = __ldcs(p + (2 * k + 2) * 32);
        pair_body(rm1, r0v, r1v, r2v);
        rm1 = r1v; r0v = r2v;
    }
    {   // rows 30,31: row 32 clamps to row 31
        float r1v = __ldcs(p + 31 * 32);
        pair_body(rm1, r0v, r1v, r1v);
    }
    __syncwarp();

    // Pairwise rotated reduce of the 32 lane-private copies per row.
    // LDS.64 at even rotated offsets: aligned; conflict-free per half-warp phase.
    // Row r (1..36) corresponds to bin r-1; rows 0 and 37 alias bins 35 and 0.
    const int rowA = lane + 1;                              // rows 1..32 (bins 0..31)
    const int rowB = (lane < 5) ? (33 + lane) : 0;          // rows 33..37, 0 (lanes 0..5)
    float sAx = 0.0f, sAy = 0.0f, sBx = 0.0f, sBy = 0.0f;
    #pragma unroll
    for (int k = 0; k < 16; ++k) {
        int x = (2 * (lane + k)) & 31;
        float2 va = *(const float2*)(hw + rowA * 32 + x);
        sAx = __fadd_rn(sAx, va.x); sAy = __fadd_rn(sAy, va.y);
        if (lane < 6) {
            float2 vb = *(const float2*)(hw + rowB * 32 + x);
            sBx = __fadd_rn(sBx, vb.x); sBy = __fadd_rn(sBy, vb.y);
        }
    }
    float s0 = __fadd_rn(sAx, sAy);
    float s1 = __fadd_rn(sBx, sBy);
    __syncwarp();
    // Diagonal slots: slot i at hw[i*32 + (i & 31)]  (bank = i mod 32)
    hw[rowA * 32 + (rowA & 31)] = s0;                       // slots 1..32
    if (lane < 6) hw[rowB * 32 + (rowB & 31)] = s1;         // slots 33..37, 0
    __syncwarp();
    // Fold aliases (appended-last add order; tolerated ordering-noise class)
    if (lane == 0) hw[1 * 32 + 1]  = __fadd_rn(hw[1 * 32 + 1],  hw[37 * 32 + 5]); // bin 0  += row37
    if (lane == 1) hw[36 * 32 + 4] = __fadd_rn(hw[36 * 32 + 4], hw[0]);           // bin 35 += row0
    __syncwarp();

    auto hbin = [&](int b) { int s = b + 1; return hw[s * 32 + (s & 31)]; };

    // sm[b] = (0.33*h[b-1] + 0.34*h[b]) + 0.33*h[b+1]  (no fma contraction)
    int bm = (lane == 0) ? 35 : lane - 1;
    int bp = lane + 1;   // lane 31 -> bin 32, valid
    float sm0 = __fadd_rn(__fadd_rn(__fmul_rn(0.33f, hbin(bm)),
                                    __fmul_rn(0.34f, hbin(lane))),
                          __fmul_rn(0.33f, hbin(bp)));
    float bv = sm0; int bi = lane;
    if (lane < 4) {
        int bb  = 32 + lane;
        int bm2 = bb - 1;
        int bp2 = (bb == 35) ? 0 : bb + 1;
        float sm1 = __fadd_rn(__fadd_rn(__fmul_rn(0.33f, hbin(bm2)),
                                        __fmul_rn(0.34f, hbin(bb))),
                              __fmul_rn(0.33f, hbin(bp2)));
        if (sm1 > bv) { bv = sm1; bi = bb; }  // strict >: tie keeps lower index
    }
    #pragma unroll
    for (int o = 16; o > 0; o >>= 1) {
        float ov = __shfl_xor_sync(FULLMASK, bv, o);
        int   oi = __shfl_xor_sync(FULLMASK, bi, o);
        if (ov > bv || (ov == bv && oi < bi)) { bv = ov; bi = oi; }
    }
    if (lane == 0) {
        float fi = (float)bi;
        float v  = __fmul_rn(6.28318530717958647692f, fi);
        v = __fdiv_rn(v, 36.0f);
        out[pIdx] = -(__fadd_rn(v, -3.14159265358979323846f));
    }
}

extern "C" void kernel_launch(void* const* d_in, const int* in_sizes, int n_in,
                              void* d_out, int out_size)
{
    cudaFuncSetAttribute(pdgo_kernel,
                         cudaFuncAttributePreferredSharedMemoryCarveout, 100);
    const float* patch = (const float*)d_in[0];
    float* out = (float*)d_out;
    int B = in_sizes[0] / 1024;      // 32*32 per patch
    int blocks = (B + 1) / 2;        // 2 warps (patches) per 64-thread block
    pdgo_kernel<<<blocks, 64>>>(patch, out, B);
}

// round 12
// speedup vs baseline: 1.0347x; 1.0347x over previous
#include <cuda_runtime.h>
#include <cuda_bf16.h>

#define FULLMASK 0xffffffffu
typedef unsigned long long u64;

// Packed f32x2 helpers (sm_103a). add/mul/fma.rn.f32x2 round each 32-bit half
// exactly like the scalar .rn ops -> bit-identical to the reference dataflow.
// fma(a, -1, b) computes b-a exactly then rounds once == rn(b-a).
__device__ __forceinline__ u64 pk(float lo, float hi) {
    u64 r; asm("mov.b64 %0,{%1,%2};" : "=l"(r) : "f"(lo), "f"(hi)); return r;
}
__device__ __forceinline__ void upk(u64 v, float& lo, float& hi) {
    asm("mov.b64 {%0,%1},%2;" : "=f"(lo), "=f"(hi) : "l"(v));
}
__device__ __forceinline__ u64 f2add(u64 a, u64 b) {
    u64 r; asm("add.rn.f32x2 %0,%1,%2;" : "=l"(r) : "l"(a), "l"(b)); return r;
}
__device__ __forceinline__ u64 f2mul(u64 a, u64 b) {
    u64 r; asm("mul.rn.f32x2 %0,%1,%2;" : "=l"(r) : "l"(a), "l"(b)); return r;
}
__device__ __forceinline__ u64 f2fma(u64 a, u64 b, u64 c) {
    u64 r; asm("fma.rn.f32x2 %0,%1,%2,%3;" : "=l"(r) : "l"(a), "l"(b), "l"(c)); return r;
}

// One warp per 32x32 patch, lane = column. Two rows per iteration, f32x2-packed
// front AND tail (R11 showed the scalar tail is slower: ptxas CSEs the pack
// boundary MOVs; keep R10's packed tail).
// 8x-scaled gradient domain (exact power-of-2; EPS pre-scaled).
// LESSON (R8): every float feeding the histogram weights follows the
// reference's exact rounding chain (rn mul/add, sqrt.rn, libdevice atan2f).
// Division by 2*pi via packed Markstein fma (correctly rounded == div.rn).
// R12: floor double-clamped to [36,71]: ob==72 re-routes exactly (w1f 0->1);
// the ulp-rare ob<36 case re-routes ~6e-8*mag of weight (incoherent noise,
// ~100x below flip threshold). -> 37-row per-lane histogram, row = floor-36,
// row r == bin r, row 36 aliases bin 0. 9472 B/block -> one more resident
// block than the 38-row layout. hist[row][lane]: bank == lane, no atomics.

__global__ void __launch_bounds__(64, 24)
pdgo_kernel(const float* __restrict__ patches, float* __restrict__ out, int B)
{
    __shared__ float hist[2][37 * 32];   // 9472 B/block

    const int warp = threadIdx.x >> 5;
    const int lane = threadIdx.x & 31;
    const int pIdx = blockIdx.x * 2 + warp;
    if (pIdx >= B) return;

    float* hw = hist[warp];
    float* hl = hw + lane;

    #pragma unroll
    for (int b = 0; b < 37; ++b) hw[b * 32 + lane] = 0.0f;
    __syncwarp();

    const float* p = patches + (size_t)pIdx * 1024 + lane;

    constexpr float C2PI   = 6.28318530717958647692f;   // f32 2*pi (0x40C90FDB)
    constexpr float RCP2PI = 1.0f / C2PI;               // rn reciprocal, folded

    const u64 TWO2   = pk(2.0f, 2.0f);
    const u64 EPS8   = pk(8e-8f, 8e-8f);     // 8 * f32(1e-8), exact scaling
    const u64 EPS64  = pk(6.4e-7f, 6.4e-7f); // 64 * f32(1e-8), exact scaling
    const u64 TWOPI2 = pk(C2PI, C2PI);
    const u64 PI2    = pk(3.14159265358979323846f, 3.14159265358979323846f);
    const u64 C36_2  = pk(36.0f, 36.0f);
    const u64 RCP2   = pk(RCP2PI, RCP2PI);
    const u64 NC2PI2 = pk(-C2PI, -C2PI);
    const u64 ONE2   = pk(1.0f, 1.0f);
    const u64 NONE2  = pk(-1.0f, -1.0f);

    // rows (r, r+1): lo half = row r, hi half = row r+1; window rm1..r2
    auto pair_body = [&](float rm1, float r0v, float r1v, float r2v) {
        u64 cv = pk(r0v, r1v);
        u64 pv = pk(rm1, r0v);
        u64 nv = pk(r1v, r2v);
        // t = (2*c + p) + n ; rn(2c+p) == rn((c+c)+p) since 2c is exact
        u64 t2x = f2add(f2fma(TWO2, cv, pv), nv);
        u64 dd2 = f2fma(pv, NONE2, nv);               // rn(n - p), exact fold

        u64 tl = __shfl_up_sync(FULLMASK, t2x, 1);    // lane0 keeps own -> edge pad
        u64 tr = __shfl_down_sync(FULLMASK, t2x, 1);  // lane31 keeps own -> edge pad
        u64 dl = __shfl_up_sync(FULLMASK, dd2, 1);
        u64 dr = __shfl_down_sync(FULLMASK, dd2, 1);

        u64 ux2 = f2fma(tl, NONE2, tr);               // rn(tr - tl) = 8*gx
        u64 uy2 = f2add(f2fma(TWO2, dd2, dl), dr);    // 8*gy

        u64 xs2 = f2add(ux2, EPS8);                   // 8*(gx+eps), exact .rn
        // m2: reference rounding order -- rn(rn(ux^2) + rn(uy^2)) + eps
        u64 m22 = f2add(f2add(f2mul(ux2, ux2), f2mul(uy2, uy2)), EPS64);

        float m2l, m2h; upk(m22, m2l, m2h);
        float magl = __fsqrt_rn(m2l), magh = __fsqrt_rn(m2h);   // 8*mag, exact
        float uyl, uyh, xsl, xsh;
        upk(uy2, uyl, uyh); upk(xs2, xsl, xsh);
        float oril = atan2f(uyl, xsl);   // == atan2f(gy, xs): scale-invariant
        float orih = atan2f(uyh, xsh);

        u64 ch = f2mul(C36_2, f2add(f2add(pk(oril, orih), TWOPI2), PI2)); // t3

        // ob = rn(t3 / 2pi) via packed Markstein sequence (correctly rounded)
        u64 q0  = f2mul(ch, RCP2);
        u64 rr  = f2fma(NC2PI2, q0, ch);              // exact residual
        u64 ob2 = f2fma(rr, RCP2, q0);

        float obl, obh; upk(ob2, obl, obh);
        // double clamp floor to [36, 71] (see header comment)
        float fbl = fminf(fmaxf(floorf(obl), 36.0f), 71.0f);
        float fbh = fminf(fmaxf(floorf(obh), 36.0f), 71.0f);
        u64 w1f2 = f2fma(pk(fbl, fbh), NONE2, ob2);   // rn(ob - fb), exact fold
        u64 mag2 = pk(magl, magh);
        u64 onem = f2fma(w1f2, NONE2, ONE2);          // rn(1 - w1f)
        u64 w0v2 = f2mul(onem, mag2);
        u64 w1v2 = f2mul(w1f2, mag2);

        float w0l, w0h, w1vl, w1vh;
        upk(w0v2, w0l, w0h); upk(w1v2, w1vl, w1vh);

        // row = floor - 36 in [0, 35]; row+1 in [1, 36]; row 36 = bin-0 alias
        int rl = (int)fbl * 32 - 36 * 32;
        hl[rl]      += w0l;
        hl[rl + 32] += w1vl;
        int rh = (int)fbh * 32 - 36 * 32;
        hl[rh]      += w0h;
        hl[rh + 32] += w1vh;
    };

    float r0v = __ldcs(p);        // row 0
    float rm1 = r0v;              // edge pad: row -1 == row 0

    #pragma unroll 3
    for (int k = 0; k < 15; ++k) {
        float r1v = __ldcs(p + (2 * k + 1) * 32);
        float r2v = __ldcs(p + (2 * k + 2) * 32);
        pair_body(rm1, r0v, r1v, r2v);
        rm1 = r1v; r0v = r2v;
    }
    {   // rows 30,31: row 32 clamps to row 31
        float r1v = __ldcs(p + 31 * 32);
        pair_body(rm1, r0v, r1v, r1v);
    }
    __syncwarp();

    // Reduce 32 lane-private copies per row. Rotated reads: bank-conflict-free.
    // Row r (0..35) is bin r; row 36 aliases bin 0, folded below.
    const int rowA = lane;                                  // rows 0..31 (bins 0..31)
    const int rowB = 32 + lane;                             // rows 32..36 (lanes 0..4)
    float s0 = 0.0f, s1 = 0.0f;
    #pragma unroll
    for (int k = 0; k < 32; ++k) {
        int l = (lane + k) & 31;
        s0 = __fadd_rn(s0, hw[rowA * 32 + l]);
        if (lane < 5) s1 = __fadd_rn(s1, hw[rowB * 32 + l]);
    }
    __syncwarp();
    // Diagonal slots: slot i at hw[i*32 + (i & 31)]  (bank = i mod 32)
    hw[rowA * 32 + (rowA & 31)] = s0;                       // slots 0..31
    if (lane < 5) hw[rowB * 32 + (rowB & 31)] = s1;         // slots 32..36
    __syncwarp();
    // Fold alias: bin 0 += row 36 (appended-last add order; tolerated class)
    if (lane == 0) hw[0] = __fadd_rn(hw[0], hw[36 * 32 + 4]);
    __syncwarp();

    auto hbin = [&](int b) { return hw[b * 32 + (b & 31)]; };

    // sm[b] = (0.33*h[b-1] + 0.34*h[b]) + 0.33*h[b+1]  (no fma contraction)
    int bm = (lane == 0) ? 35 : lane - 1;
    int bp = lane + 1;   // lane 31 -> bin 32, valid
    float sm0 = __fadd_rn(__fadd_rn(__fmul_rn(0.33f, hbin(bm)),
                                    __fmul_rn(0.34f, hbin(lane))),
                          __fmul_rn(0.33f, hbin(bp)));
    float bv = sm0; int bi = lane;
    if (lane < 4) {
        int bb  = 32 + lane;
        int bm2 = bb - 1;
        int bp2 = (bb == 35) ? 0 : bb + 1;
        float sm1 = __fadd_rn(__fadd_rn(__fmul_rn(0.33f, hbin(bm2)),
                                        __fmul_rn(0.34f, hbin(bb))),
                              __fmul_rn(0.33f, hbin(bp2)));
        if (sm1 > bv) { bv = sm1; bi = bb; }  // strict >: tie keeps lower index
    }
    #pragma unroll
    for (int o = 16; o > 0; o >>= 1) {
        float ov = __shfl_xor_sync(FULLMASK, bv, o);
        int   oi = __shfl_xor_sync(FULLMASK, bi, o);
        if (ov > bv || (ov == bv && oi < bi)) { bv = ov; bi = oi; }
    }
    if (lane == 0) {
        float fi = (float)bi;
        float v  = __fmul_rn(6.28318530717958647692f, fi);
        v = __fdiv_rn(v, 36.0f);
        out[pIdx] = -(__fadd_rn(v, -3.14159265358979323846f));
    }
}

extern "C" void kernel_launch(void* const* d_in, const int* in_sizes, int n_in,
                              void* d_out, int out_size)
{
    cudaFuncSetAttribute(pdgo_kernel,
                         cudaFuncAttributePreferredSharedMemoryCarveout, 100);
    const float* patch = (const float*)d_in[0];
    float* out = (float*)d_out;
    int B = in_sizes[0] / 1024;      // 32*32 per patch
    int blocks = (B + 1) / 2;        // 2 warps (patches) per 64-thread block
    pdgo_kernel<<<blocks, 64>>>(patch, out, B);
}

// round 13
// speedup vs baseline: 1.0528x; 1.0175x over previous
#include <cuda_runtime.h>
#include <cuda_bf16.h>

#define FULLMASK 0xffffffffu
typedef unsigned long long u64;

// Packed f32x2 helpers (sm_103a). add/mul/fma.rn.f32x2 round each 32-bit half
// exactly like the scalar .rn ops -> bit-identical to the reference dataflow.
// fma(a, -1, b) computes b-a exactly then rounds once == rn(b-a).
__device__ __forceinline__ u64 pk(float lo, float hi) {
    u64 r; asm("mov.b64 %0,{%1,%2};" : "=l"(r) : "f"(lo), "f"(hi)); return r;
}
__device__ __forceinline__ void upk(u64 v, float& lo, float& hi) {
    asm("mov.b64 {%0,%1},%2;" : "=f"(lo), "=f"(hi) : "l"(v));
}
__device__ __forceinline__ u64 f2add(u64 a, u64 b) {
    u64 r; asm("add.rn.f32x2 %0,%1,%2;" : "=l"(r) : "l"(a), "l"(b)); return r;
}
__device__ __forceinline__ u64 f2mul(u64 a, u64 b) {
    u64 r; asm("mul.rn.f32x2 %0,%1,%2;" : "=l"(r) : "l"(a), "l"(b)); return r;
}
__device__ __forceinline__ u64 f2fma(u64 a, u64 b, u64 c) {
    u64 r; asm("fma.rn.f32x2 %0,%1,%2,%3;" : "=l"(r) : "l"(a), "l"(b), "l"(c)); return r;
}

// One warp per 32x32 patch, lane = column. Two rows per iteration, f32x2-packed
// front and tail (R11: scalar tail is slower; ptxas CSEs pack-boundary MOVs).
// 8x-scaled gradient domain (exact power-of-2; EPS pre-scaled).
// LESSON (R8): every float feeding the histogram weights follows the
// reference's exact rounding chain (rn mul/add, sqrt.rn, libdevice atan2f).
// Division by 2*pi via packed Markstein fma (correctly rounded == div.rn).
// floor double-clamped to [36,71]: ob==72 re-routes exactly (w1f 0->1); the
// ulp-rare ob<36 case re-routes ~6e-8*mag (incoherent, ~100x below flip
// threshold). 37-row per-lane histogram, row = floor-36, row r == bin r,
// row 36 aliases bin 0. 9472 B/block -> 24 blocks/SM (48 warps theoretical).
// hist[row][lane]: bank == lane, conflict-free, no atomics.
// R13: float4 hist init (10 STS.128 vs 37 STS.32), 2-accumulator rotated
// reduce (halves the serial FADD chain), unroll 5 for more independent
// atan2/sqrt chains in flight.

__global__ void __launch_bounds__(64, 24)
pdgo_kernel(const float* __restrict__ patches, float* __restrict__ out, int B)
{
    __shared__ float hist[2][37 * 32];   // 9472 B/block

    const int warp = threadIdx.x >> 5;
    const int lane = threadIdx.x & 31;
    const int pIdx = blockIdx.x * 2 + warp;
    if (pIdx >= B) return;

    float* hw = hist[warp];
    float* hl = hw + lane;

    // Flattened init: 1184 floats = 296 float4; lanes cover 32/iter, 9 full + tail
    {
        float4 z = make_float4(0.0f, 0.0f, 0.0f, 0.0f);
        float4* h4 = (float4*)hw;
        #pragma unroll
        for (int i = 0; i < 9; ++i) h4[i * 32 + lane] = z;
        if (lane < 8) h4[9 * 32 + lane] = z;
    }
    __syncwarp();

    const float* p = patches + (size_t)pIdx * 1024 + lane;

    constexpr float C2PI   = 6.28318530717958647692f;   // f32 2*pi (0x40C90FDB)
    constexpr float RCP2PI = 1.0f / C2PI;               // rn reciprocal, folded

    const u64 TWO2   = pk(2.0f, 2.0f);
    const u64 EPS8   = pk(8e-8f, 8e-8f);     // 8 * f32(1e-8), exact scaling
    const u64 EPS64  = pk(6.4e-7f, 6.4e-7f); // 64 * f32(1e-8), exact scaling
    const u64 TWOPI2 = pk(C2PI, C2PI);
    const u64 PI2    = pk(3.14159265358979323846f, 3.14159265358979323846f);
    const u64 C36_2  = pk(36.0f, 36.0f);
    const u64 RCP2   = pk(RCP2PI, RCP2PI);
    const u64 NC2PI2 = pk(-C2PI, -C2PI);
    const u64 ONE2   = pk(1.0f, 1.0f);
    const u64 NONE2  = pk(-1.0f, -1.0f);

    // rows (r, r+1): lo half = row r, hi half = row r+1; window rm1..r2
    auto pair_body = [&](float rm1, float r0v, float r1v, float r2v) {
        u64 cv = pk(r0v, r1v);
        u64 pv = pk(rm1, r0v);
        u64 nv = pk(r1v, r2v);
        // t = (2*c + p) + n ; rn(2c+p) == rn((c+c)+p) since 2c is exact
        u64 t2x = f2add(f2fma(TWO2, cv, pv), nv);
        u64 dd2 = f2fma(pv, NONE2, nv);               // rn(n - p), exact fold

        u64 tl = __shfl_up_sync(FULLMASK, t2x, 1);    // lane0 keeps own -> edge pad
        u64 tr = __shfl_down_sync(FULLMASK, t2x, 1);  // lane31 keeps own -> edge pad
        u64 dl = __shfl_up_sync(FULLMASK, dd2, 1);
        u64 dr = __shfl_down_sync(FULLMASK, dd2, 1);

        u64 ux2 = f2fma(tl, NONE2, tr);               // rn(tr - tl) = 8*gx
        u64 uy2 = f2add(f2fma(TWO2, dd2, dl), dr);    // 8*gy

        u64 xs2 = f2add(ux2, EPS8);                   // 8*(gx+eps), exact .rn
        // m2: reference rounding order -- rn(rn(ux^2) + rn(uy^2)) + eps
        u64 m22 = f2add(f2add(f2mul(ux2, ux2), f2mul(uy2, uy2)), EPS64);

        float m2l, m2h; upk(m22, m2l, m2h);
        float magl = __fsqrt_rn(m2l), magh = __fsqrt_rn(m2h);   // 8*mag, exact
        float uyl, uyh, xsl, xsh;
        upk(uy2, uyl, uyh); upk(xs2, xsl, xsh);
        float oril = atan2f(uyl, xsl);   // == atan2f(gy, xs): scale-invariant
        float orih = atan2f(uyh, xsh);

        u64 ch = f2mul(C36_2, f2add(f2add(pk(oril, orih), TWOPI2), PI2)); // t3

        // ob = rn(t3 / 2pi) via packed Markstein sequence (correctly rounded)
        u64 q0  = f2mul(ch, RCP2);
        u64 rr  = f2fma(NC2PI2, q0, ch);              // exact residual
        u64 ob2 = f2fma(rr, RCP2, q0);

        float obl, obh; upk(ob2, obl, obh);
        // double clamp floor to [36, 71] (see header comment)
        float fbl = fminf(fmaxf(floorf(obl), 36.0f), 71.0f);
        float fbh = fminf(fmaxf(floorf(obh), 36.0f), 71.0f);
        u64 w1f2 = f2fma(pk(fbl, fbh), NONE2, ob2);   // rn(ob - fb), exact fold
        u64 mag2 = pk(magl, magh);
        u64 onem = f2fma(w1f2, NONE2, ONE2);          // rn(1 - w1f)
        u64 w0v2 = f2mul(onem, mag2);
        u64 w1v2 = f2mul(w1f2, mag2);

        float w0l, w0h, w1vl, w1vh;
        upk(w0v2, w0l, w0h); upk(w1v2, w1vl, w1vh);

        // row = floor - 36 in [0, 35]; row+1 in [1, 36]; row 36 = bin-0 alias
        int rl = (int)fbl * 32 - 36 * 32;
        hl[rl]      += w0l;
        hl[rl + 32] += w1vl;
        int rh = (int)fbh * 32 - 36 * 32;
        hl[rh]      += w0h;
        hl[rh + 32] += w1vh;
    };

    float r0v = __ldcs(p);        // row 0
    float rm1 = r0v;              // edge pad: row -1 == row 0

    #pragma unroll 5
    for (int k = 0; k < 15; ++k) {
        float r1v = __ldcs(p + (2 * k + 1) * 32);
        float r2v = __ldcs(p + (2 * k + 2) * 32);
        pair_body(rm1, r0v, r1v, r2v);
        rm1 = r1v; r0v = r2v;
    }
    {   // rows 30,31: row 32 clamps to row 31
        float r1v = __ldcs(p + 31 * 32);
        pair_body(rm1, r0v, r1v, r1v);
    }
    __syncwarp();

    // Reduce 32 lane-private copies per row; rotated reads (conflict-free),
    // 2 independent accumulators halve the serial FADD chain (ordering-noise
    // class, tolerated).
    const int rowA = lane;                                  // rows 0..31 (bins 0..31)
    const int rowB = 32 + lane;                             // rows 32..36 (lanes 0..4)
    float sA0 = 0.0f, sA1 = 0.0f, sB0 = 0.0f, sB1 = 0.0f;
    #pragma unroll
    for (int k = 0; k < 32; k += 2) {
        int l0 = (lane + k) & 31;
        int l1 = (lane + k + 1) & 31;
        sA0 = __fadd_rn(sA0, hw[rowA * 32 + l0]);
        sA1 = __fadd_rn(sA1, hw[rowA * 32 + l1]);
        if (lane < 5) {
            sB0 = __fadd_rn(sB0, hw[rowB * 32 + l0]);
            sB1 = __fadd_rn(sB1, hw[rowB * 32 + l1]);
        }
    }
    float s0 = __fadd_rn(sA0, sA1);
    float s1 = __fadd_rn(sB0, sB1);
    __syncwarp();
    // Diagonal slots: slot i at hw[i*32 + (i & 31)]  (bank = i mod 32)
    hw[rowA * 32 + (rowA & 31)] = s0;                       // slots 0..31
    if (lane < 5) hw[rowB * 32 + (rowB & 31)] = s1;         // slots 32..36
    __syncwarp();
    // Fold alias: bin 0 += row 36 (appended-last add order; tolerated class)
    if (lane == 0) hw[0] = __fadd_rn(hw[0], hw[36 * 32 + 4]);
    __syncwarp();

    auto hbin = [&](int b) { return hw[b * 32 + (b & 31)]; };

    // sm[b] = (0.33*h[b-1] + 0.34*h[b]) + 0.33*h[b+1]  (no fma contraction)
    int bm = (lane == 0) ? 35 : lane - 1;
    int bp = lane + 1;   // lane 31 -> bin 32, valid
    float sm0 = __fadd_rn(__fadd_rn(__fmul_rn(0.33f, hbin(bm)),
                                    __fmul_rn(0.34f, hbin(lane))),
                          __fmul_rn(0.33f, hbin(bp)));
    float bv = sm0; int bi = lane;
    if (lane < 4) {
        int bb  = 32 + lane;
        int bm2 = bb - 1;
        int bp2 = (bb == 35) ? 0 : bb + 1;
        float sm1 = __fadd_rn(__fadd_rn(__fmul_rn(0.33f, hbin(bm2)),
                                        __fmul_rn(0.34f, hbin(bb))),
                              __fmul_rn(0.33f, hbin(bp2)));
        if (sm1 > bv) { bv = sm1; bi = bb; }  // strict >: tie keeps lower index
    }
    #pragma unroll
    for (int o = 16; o > 0; o >>= 1) {
        float ov = __shfl_xor_sync(FULLMASK, bv, o);
        int   oi = __shfl_xor_sync(FULLMASK, bi, o);
        if (ov > bv || (ov == bv && oi < bi)) { bv = ov; bi = oi; }
    }
    if (lane == 0) {
        float fi = (float)bi;
        float v  = __fmul_rn(6.28318530717958647692f, fi);
        v = __fdiv_rn(v, 36.0f);
        out[pIdx] = -(__fadd_rn(v, -3.14159265358979323846f));
    }
}

extern "C" void kernel_launch(void* const* d_in, const int* in_sizes, int n_in,
                              void* d_out, int out_size)
{
    cudaFuncSetAttribute(pdgo_kernel,
                         cudaFuncAttributePreferredSharedMemoryCarveout, 100);
    const float* patch = (const float*)d_in[0];
    float* out = (float*)d_out;
    int B = in_sizes[0] / 1024;      // 32*32 per patch
    int blocks = (B + 1) / 2;        // 2 warps (patches) per 64-thread block
    pdgo_kernel<<<blocks, 64>>>(patch, out, B);
}